// round 15
// baseline (speedup 1.0000x reference)
#include <cuda_runtime.h>
#include <cuda_fp16.h>
#include <cstdint>

#define T_STEPS 784
#define BATCH   512
#define HID     200
#define G4      800
#define NCTA    128
#define THREADS 256
#define UNITS_PER 25
#define BT_ROWS 64
#define KC_N    13              // ceil(200/16) k-chunks of 16
#define NSUB    13              // gate-interleaved packed N = 104 (100 real)
#define FRAG_U32 (KC_N*4*32*4)  // 6656 uint32 words per (parity,dir,bt) block

// ---------------- device global scratch (static, no allocation) ----------------
__device__ float g_u[2][G4];
__device__ float g_v[2][G4];
__device__ uint32_t g_hfrag[2][2][8][FRAG_U32];   // fp16x2 A-fragment words
__device__ float g_hpart[2][8][T_STEPS][HID];     // per-(dir,bt) batch partial sums

// ---------------- smem layout (bytes) ----------------
#define GSTRIDE 108       // floats per Gbuf row (104 used, mult of 4 for float4)
#define BP_OFF 0          // uint2 [13][13][32]    43264
#define GB_OFF 43264      // float [64][108]       27648
#define HS_OFF 70912      // float [64][26]         6656
#define SU_OFF 77568      // float4 [26]             416
#define SV_OFF 77984      // float4 [26]             416
#define MB_OFF 78400      // mbarrier (8B, padded 16)
#define SMEM_BYTES 78416

__device__ __forceinline__ float tanha(float x) {
    float r;
    asm("tanh.approx.f32 %0, %1;" : "=f"(r) : "f"(x));
    return r;
}
__device__ __forceinline__ float sigf(float x) {
    return fmaf(0.5f, tanha(0.5f * x), 0.5f);
}
__device__ __forceinline__ uint32_t pack_h2(float lo, float hi) {
    __half2 h = __floats2half2_rn(lo, hi);
    return *(uint32_t*)&h;
}
__device__ __forceinline__ uint4 ldg_cg_v4(const uint32_t* p) {
    uint4 v;
    asm volatile("ld.global.cg.v4.u32 {%0,%1,%2,%3}, [%4];"
                 : "=r"(v.x), "=r"(v.y), "=r"(v.z), "=r"(v.w) : "l"(p));
    return v;
}
__device__ __forceinline__ uint32_t smem_u32(const void* p) {
    uint32_t a;
    asm("{ .reg .u64 t; cvta.to.shared.u64 t, %1; cvt.u32.u64 %0, t; }"
        : "=r"(a) : "l"(p));
    return a;
}

// remote arrive on cluster CTA `rank`'s mbarrier at same smem offset
#define MBAR_ARRIVE_REMOTE(mbar, rank)                                   \
    asm volatile(                                                        \
        "{\n\t.reg .b32 ra;\n\t"                                         \
        "mapa.shared::cluster.u32 ra, %0, %1;\n\t"                       \
        "mbarrier.arrive.release.cluster.shared::cluster.b64 _, [ra];\n\t}" \
        :: "r"(mbar), "r"(rank) : "memory")

// cluster-scope acquire parity wait
#define MBAR_WAIT_CLUSTER(mbar, parity)                                              \
    asm volatile(                                                                    \
        "{\n\t.reg .pred P;\n\t"                                                     \
        "WAITLOOP%=:\n\t"                                                            \
        "mbarrier.try_wait.parity.acquire.cluster.shared::cta.b64 P, [%0], %1, 0x989680;\n\t" \
        "@!P bra WAITLOOP%=;\n\t}"                                                   \
        :: "r"(mbar), "r"(parity) : "memory")

// ---------------- Phase B+C: m16 x n(8*JCNT), spill to Gbuf ----------------
template<int JCNT>
__device__ __forceinline__ void phaseBC(const uint32_t* __restrict__ fin,
                                        const uint2* __restrict__ Bp,
                                        float* __restrict__ Gbuf,
                                        int mt, int jbase, int lane) {
    const int ab = ((mt << 5) | lane) * 4;
    uint4 areg[KC_N];
    #pragma unroll
    for (int kc = 0; kc < KC_N; kc++)
        areg[kc] = ldg_cg_v4(fin + ab + kc * 512);

    float acc[JCNT][4];
    #pragma unroll
    for (int j = 0; j < JCNT; j++)
        acc[j][0] = acc[j][1] = acc[j][2] = acc[j][3] = 0.f;

    #pragma unroll
    for (int kc = 0; kc < KC_N; kc++) {
        uint2 bb[JCNT];
        #pragma unroll
        for (int j = 0; j < JCNT; j++)
            bb[j] = Bp[(kc * NSUB + jbase + j) * 32 + lane];
        #pragma unroll
        for (int j = 0; j < JCNT; j++) {
            asm volatile(
                "mma.sync.aligned.m16n8k16.row.col.f32.f16.f16.f32 "
                "{%0,%1,%2,%3}, {%4,%5,%6,%7}, {%8,%9}, {%0,%1,%2,%3};\n"
                : "+f"(acc[j][0]), "+f"(acc[j][1]), "+f"(acc[j][2]), "+f"(acc[j][3])
                : "r"(areg[kc].x), "r"(areg[kc].y), "r"(areg[kc].z), "r"(areg[kc].w),
                  "r"(bb[j].x), "r"(bb[j].y));
        }
    }
    int g = lane >> 2, tg = lane & 3;
    int row0 = mt * 16 + g;
    #pragma unroll
    for (int j = 0; j < JCNT; j++) {
        int col = (jbase + j) * 8 + tg * 2;
        *(float2*)&Gbuf[row0 * GSTRIDE + col]       = make_float2(acc[j][0], acc[j][1]);
        *(float2*)&Gbuf[(row0 + 8) * GSTRIDE + col] = make_float2(acc[j][2], acc[j][3]);
    }
}

// ---------------- precompute: rank-1 input-gate vectors + zeroing ----------------
__global__ void precompute_kernel(const float* __restrict__ W_in,
                                  const float* __restrict__ b_in,
                                  const float* __restrict__ Wih_f,
                                  const float* __restrict__ b_f,
                                  const float* __restrict__ Wih_b,
                                  const float* __restrict__ b_b) {
    int idx = blockIdx.x * blockDim.x + threadIdx.x;
    int nth = gridDim.x * blockDim.x;
    for (int i = idx; i < 2 * G4; i += nth) {
        int dir = i / G4, row = i % G4;
        const float* Wih = dir ? Wih_b : Wih_f;
        const float* bb  = dir ? b_b   : b_f;
        float su = 0.f, sv = 0.f;
        for (int k = 0; k < HID; k++) {
            float w = Wih[row * HID + k];
            su += w * W_in[k];
            sv += w * b_in[k];
        }
        g_u[dir][row] = su;
        g_v[dir][row] = sv + bb[row];
    }
    uint32_t* hf = &g_hfrag[0][0][0][0];
    for (int i = idx; i < 2 * 2 * 8 * FRAG_U32; i += nth) hf[i] = 0u;
}

// ---------------- persistent recurrence kernel: 16 clusters of 8 CTAs ----------------
__global__ void __launch_bounds__(THREADS, 1) __cluster_dims__(8, 1, 1)
lstm_kernel(const float* __restrict__ x,
            const float* __restrict__ Whh_f,
            const float* __restrict__ Whh_b) {
    extern __shared__ unsigned char smem_raw[];
    uint2*  Bp   = (uint2*) (smem_raw + BP_OFF);
    float*  Gbuf = (float*) (smem_raw + GB_OFF);
    float*  hsb  = (float*) (smem_raw + HS_OFF);
    float4* su4  = (float4*)(smem_raw + SU_OFF);
    float4* sv4  = (float4*)(smem_raw + SV_OFF);
    float*  su4f = (float*)su4;
    float*  sv4f = (float*)sv4;
    const uint32_t mbar = smem_u32(smem_raw) + MB_OFF;

    const int tid = threadIdx.x;
    const int cta = blockIdx.x;
    const int dir = cta >> 6;
    const int bt  = (cta >> 3) & 7;
    const int ut  = cta & 7;
    const int j0  = ut * UNITS_PER;
    const float* Whh = dir ? Whh_b : Whh_f;

    // ---- prologue: gate vectors, Whh B-frags, mbarrier init ----
    if (tid == 0) {
        asm volatile("mbarrier.init.shared.b64 [%0], %1;"
                     :: "r"(mbar), "r"(8u) : "memory");
    }
    for (int i = tid; i < 104; i += THREADS) {
        float uu = 0.f, vv = 0.f;
        if (i < 100) {
            int u = i >> 2, gate = i & 3;
            int row = gate * HID + j0 + u;
            uu = g_u[dir][row];
            vv = g_v[dir][row];
        }
        su4f[i] = uu;
        sv4f[i] = vv;
    }
    // Bp[(kc*13+nsub)*32+lane]: b0 = fp16x2{W(n,k0),W(n,k0+1)}, b1 = {W(n,k0+8),W(n,k0+9)}
    // gate-interleaved packed n = nsub*8 + (lane>>2): u = n>>2, gate = n&3
    for (int i = tid; i < KC_N * NSUB * 32; i += THREADS) {
        int kc = i / (NSUB * 32);
        int r  = i % (NSUB * 32);
        int nsub = r >> 5;
        int lane = r & 31;
        int g = lane >> 2, tg = lane & 3;
        int n = nsub * 8 + g;
        int u = n >> 2, gate = n & 3;
        float w0 = 0.f, w1 = 0.f, w2 = 0.f, w3 = 0.f;
        if (u < UNITS_PER) {
            int row = gate * HID + j0 + u;
            int k0 = kc * 16 + 2 * tg;
            const float* wr = &Whh[row * HID];
            if (k0     < HID) w0 = wr[k0];
            if (k0 + 1 < HID) w1 = wr[k0 + 1];
            if (k0 + 8 < HID) w2 = wr[k0 + 8];
            if (k0 + 9 < HID) w3 = wr[k0 + 9];
        }
        Bp[i] = make_uint2(pack_h2(w0, w1), pack_h2(w2, w3));
    }
    __syncthreads();
    // publish mbarrier inits + initial h state across the cluster
    asm volatile("barrier.cluster.arrive.aligned;" ::: "memory");
    asm volatile("barrier.cluster.wait.aligned;" ::: "memory");

    const int warp = tid >> 5;
    const int lane = tid & 31;
    const int mt = warp & 3;   // m16 tile within 64 rows
    const int nh = warp >> 2;  // 0: subtiles 0-6, 1: subtiles 7-12
    const int qd = tid >> 6;   // Phase D: u ≡ qd (mod 4)
    const int bd = tid & 63;   // Phase D: fixed batch row
    const int ue = tid >> 3;   // Phase E unit
    const int seg = tid & 7;   // Phase E batch segment

    float creg[7];
    #pragma unroll
    for (int j = 0; j < 7; j++) creg[j] = 0.f;

    for (int s = 0; s < T_STEPS; s++) {
        const int p = s & 1;
        const int t = dir ? (T_STEPS - 1 - s) : s;
        const uint32_t* fin = &g_hfrag[p][dir][bt][0];
        unsigned short* fout = (unsigned short*)&g_hfrag[p ^ 1][dir][bt][0];

        // per-thread x scalar for Phase D (issued early, hides behind MMA)
        const float xi = __ldg(&x[t * BATCH + bt * BT_ROWS + bd]);

        // ---- Phase B+C: MMA into gate-interleaved Gbuf ----
        if (nh == 0) phaseBC<7>(fin, Bp, Gbuf, mt, 0, lane);
        else         phaseBC<6>(fin, Bp, Gbuf, mt, 7, lane);
        __syncthreads();

        // ---- Phase D: fixed (b, u-set) per thread; c in registers ----
        {
            const float* grow = &Gbuf[bd * GSTRIDE];
            #pragma unroll
            for (int jj = 0; jj < 7; jj++) {
                int u = qd + jj * 4;
                if (u < UNITS_PER) {
                    float4 gq = *(const float4*)&grow[4 * u];
                    float4 a4 = su4[u];
                    float4 v4 = sv4[u];
                    float gi = gq.x + xi * a4.x + v4.x;
                    float gf = gq.y + xi * a4.y + v4.y;
                    float gg = gq.z + xi * a4.z + v4.z;
                    float go = gq.w + xi * a4.w + v4.w;
                    float cn = sigf(gf) * creg[jj] + sigf(gi) * tanha(gg);
                    creg[jj] = cn;
                    float h = sigf(go) * tanha(cn);
                    hsb[bd * 26 + u] = h;
                    // fp16 fragment half address for (bd, k=j0+u)
                    int k = j0 + u;
                    int mtt = bd >> 4, g2 = bd & 7, rb = (bd >> 3) & 1;
                    int kc = k >> 4, km = k & 15;
                    int tg = (km >> 1) & 3, kb = km >> 3, half = k & 1;
                    int ln = (g2 << 2) | tg;
                    int reg = (kb << 1) | rb;
                    int idx16 = ((((kc * 4 + mtt) << 5) | ln) * 4 + reg) * 2 + half;
                    __half hh = __float2half_rn(h);
                    fout[idx16] = *(unsigned short*)&hh;
                }
            }
        }
        __syncthreads();   // all h-frag stores + hsb visible CTA-wide

        // ---- release + arrive on all 8 cluster CTAs (fire-and-forget) ----
        if (tid == 0) {
            asm volatile("fence.acq_rel.cluster;" ::: "memory");
            #pragma unroll
            for (int r = 0; r < 8; r++) MBAR_ARRIVE_REMOTE(mbar, r);
        }

        // ---- Phase E: batch partial sums (shuffle reduce, no psum/sync) ----
        {
            float sum = 0.f;
            if (ue < UNITS_PER) {
                #pragma unroll
                for (int b = 0; b < 8; b++) sum += hsb[(seg * 8 + b) * 26 + ue];
            }
            sum += __shfl_down_sync(0xffffffffu, sum, 4, 8);
            sum += __shfl_down_sync(0xffffffffu, sum, 2, 8);
            sum += __shfl_down_sync(0xffffffffu, sum, 1, 8);
            if (ue < UNITS_PER && seg == 0)
                g_hpart[dir][bt][t][j0 + ue] = sum;
        }

        // ---- wait: 8 arrivals (cluster acquire) ----
        MBAR_WAIT_CLUSTER(mbar, s & 1);
    }

    // teardown safety: no CTA exits with peers' remote ops possibly in flight
    asm volatile("barrier.cluster.arrive.aligned;" ::: "memory");
    asm volatile("barrier.cluster.wait.aligned;" ::: "memory");
}

// ---------------- finalize: reduce partials over bt, apply linear head ----------------
__global__ void finalize_kernel(const float* __restrict__ W_fc,
                                const float* __restrict__ b_fc,
                                float* __restrict__ out) {
    __shared__ float hb[2 * HID];
    int t = blockIdx.x;
    int tid = threadIdx.x;
    for (int j = tid; j < 2 * HID; j += blockDim.x) {
        int dir = j / HID, jj = j - dir * HID;
        float sum = 0.f;
        #pragma unroll
        for (int b = 0; b < 8; b++) sum += g_hpart[dir][b][t][jj];
        hb[j] = sum;
    }
    __syncthreads();
    if (tid < 10) {
        const float* wf = &W_fc[tid * (2 * HID)];
        float acc = 0.f;
        for (int j = 0; j < 2 * HID; j++) acc += wf[j] * hb[j];
        out[t * 10 + tid] = b_fc[tid] + acc * (1.f / 512.f);
    }
}

extern "C" void kernel_launch(void* const* d_in, const int* in_sizes, int n_in,
                              void* d_out, int out_size) {
    const float* x     = (const float*)d_in[0];
    const float* W_in  = (const float*)d_in[1];
    const float* b_in  = (const float*)d_in[2];
    const float* Wih_f = (const float*)d_in[3];
    const float* Whh_f = (const float*)d_in[4];
    const float* b_f   = (const float*)d_in[5];
    const float* Wih_b = (const float*)d_in[6];
    const float* Whh_b = (const float*)d_in[7];
    const float* b_b   = (const float*)d_in[8];
    const float* W_fc  = (const float*)d_in[9];
    const float* b_fc  = (const float*)d_in[10];
    float* out = (float*)d_out;

    cudaFuncSetAttribute(lstm_kernel,
                         cudaFuncAttributeMaxDynamicSharedMemorySize, SMEM_BYTES);

    precompute_kernel<<<32, 256>>>(W_in, b_in, Wih_f, b_f, Wih_b, b_b);
    lstm_kernel<<<NCTA, THREADS, SMEM_BYTES>>>(x, Whh_f, Whh_b);
    finalize_kernel<<<T_STEPS, 256>>>(W_fc, b_fc, out);
}

// round 16
// speedup vs baseline: 1.3817x; 1.3817x over previous
#include <cuda_runtime.h>
#include <cuda_fp16.h>
#include <cstdint>

#define T_STEPS 784
#define BATCH   512
#define HID     200
#define G4      800
#define NCTA    128
#define THREADS 256
#define UNITS_PER 25
#define BT_ROWS 64
#define KC_N    13              // ceil(200/16) k-chunks of 16
#define NSUB    13              // gate-interleaved packed N = 104 (100 real)
#define FRAG_U32 (KC_N*4*32*4)  // 6656 uint32 words per (parity,dir,bt) block

// ---------------- device global scratch (static, no allocation) ----------------
__device__ float g_u[2][G4];
__device__ float g_v[2][G4];
__device__ uint32_t g_hfrag[2][2][8][FRAG_U32];   // fp16x2 A-fragment words
__device__ float g_hpart[2][8][T_STEPS][HID];     // batch sums (red.add targets)

// ---------------- smem layout (bytes) ----------------
#define GSTRIDE 108       // floats per Gbuf row (104 used, mult of 4 for float4)
#define BP_OFF 0          // uint2 [13][13][32]    43264
#define GB_OFF 43264      // float [64][108]       27648
#define SU_OFF 70912      // float4 [26]             416
#define SV_OFF 71328      // float4 [26]             416
#define SMEM_BYTES 71744

__device__ __forceinline__ float tanha(float x) {
    float r;
    asm("tanh.approx.f32 %0, %1;" : "=f"(r) : "f"(x));
    return r;
}
__device__ __forceinline__ float sigf(float x) {
    return fmaf(0.5f, tanha(0.5f * x), 0.5f);
}
__device__ __forceinline__ uint32_t pack_h2(float lo, float hi) {
    __half2 h = __floats2half2_rn(lo, hi);
    return *(uint32_t*)&h;
}
__device__ __forceinline__ uint4 ldg_cg_v4(const uint32_t* p) {
    uint4 v;
    asm volatile("ld.global.cg.v4.u32 {%0,%1,%2,%3}, [%4];"
                 : "=r"(v.x), "=r"(v.y), "=r"(v.z), "=r"(v.w) : "l"(p));
    return v;
}

// ---------------- Phase B+C: m16 x n(8*JCNT), spill to Gbuf ----------------
template<int JCNT>
__device__ __forceinline__ void phaseBC(const uint32_t* __restrict__ fin,
                                        const uint2* __restrict__ Bp,
                                        float* __restrict__ Gbuf,
                                        int mt, int jbase, int lane) {
    const int ab = ((mt << 5) | lane) * 4;
    uint4 areg[KC_N];
    #pragma unroll
    for (int kc = 0; kc < KC_N; kc++)
        areg[kc] = ldg_cg_v4(fin + ab + kc * 512);

    float acc[JCNT][4];
    #pragma unroll
    for (int j = 0; j < JCNT; j++)
        acc[j][0] = acc[j][1] = acc[j][2] = acc[j][3] = 0.f;

    #pragma unroll
    for (int kc = 0; kc < KC_N; kc++) {
        uint2 bb[JCNT];
        #pragma unroll
        for (int j = 0; j < JCNT; j++)
            bb[j] = Bp[(kc * NSUB + jbase + j) * 32 + lane];
        #pragma unroll
        for (int j = 0; j < JCNT; j++) {
            asm volatile(
                "mma.sync.aligned.m16n8k16.row.col.f32.f16.f16.f32 "
                "{%0,%1,%2,%3}, {%4,%5,%6,%7}, {%8,%9}, {%0,%1,%2,%3};\n"
                : "+f"(acc[j][0]), "+f"(acc[j][1]), "+f"(acc[j][2]), "+f"(acc[j][3])
                : "r"(areg[kc].x), "r"(areg[kc].y), "r"(areg[kc].z), "r"(areg[kc].w),
                  "r"(bb[j].x), "r"(bb[j].y));
        }
    }
    int g = lane >> 2, tg = lane & 3;
    int row0 = mt * 16 + g;
    #pragma unroll
    for (int j = 0; j < JCNT; j++) {
        int col = (jbase + j) * 8 + tg * 2;
        *(float2*)&Gbuf[row0 * GSTRIDE + col]       = make_float2(acc[j][0], acc[j][1]);
        *(float2*)&Gbuf[(row0 + 8) * GSTRIDE + col] = make_float2(acc[j][2], acc[j][3]);
    }
}

// ---------------- precompute: rank-1 input-gate vectors + zeroing ----------------
__global__ void precompute_kernel(const float* __restrict__ W_in,
                                  const float* __restrict__ b_in,
                                  const float* __restrict__ Wih_f,
                                  const float* __restrict__ b_f,
                                  const float* __restrict__ Wih_b,
                                  const float* __restrict__ b_b) {
    int idx = blockIdx.x * blockDim.x + threadIdx.x;
    int nth = gridDim.x * blockDim.x;
    for (int i = idx; i < 2 * G4; i += nth) {
        int dir = i / G4, row = i % G4;
        const float* Wih = dir ? Wih_b : Wih_f;
        const float* bb  = dir ? b_b   : b_f;
        float su = 0.f, sv = 0.f;
        for (int k = 0; k < HID; k++) {
            float w = Wih[row * HID + k];
            su += w * W_in[k];
            sv += w * b_in[k];
        }
        g_u[dir][row] = su;
        g_v[dir][row] = sv + bb[row];
    }
    uint32_t* hf = &g_hfrag[0][0][0][0];
    for (int i = idx; i < 2 * 2 * 8 * FRAG_U32; i += nth) hf[i] = 0u;
    float* hp = &g_hpart[0][0][0][0];
    for (int i = idx; i < 2 * 8 * T_STEPS * HID; i += nth) hp[i] = 0.f;
}

// ---------------- persistent recurrence kernel: 16 clusters of 8 CTAs ----------------
__global__ void __launch_bounds__(THREADS, 1) __cluster_dims__(8, 1, 1)
lstm_kernel(const float* __restrict__ x,
            const float* __restrict__ Whh_f,
            const float* __restrict__ Whh_b) {
    extern __shared__ unsigned char smem_raw[];
    uint2*  Bp   = (uint2*) (smem_raw + BP_OFF);
    float*  Gbuf = (float*) (smem_raw + GB_OFF);
    float4* su4  = (float4*)(smem_raw + SU_OFF);
    float4* sv4  = (float4*)(smem_raw + SV_OFF);
    float*  su4f = (float*)su4;
    float*  sv4f = (float*)sv4;

    const int tid = threadIdx.x;
    const int cta = blockIdx.x;
    const int dir = cta >> 6;
    const int bt  = (cta >> 3) & 7;
    const int ut  = cta & 7;
    const int j0  = ut * UNITS_PER;
    const float* Whh = dir ? Whh_b : Whh_f;

    // ---- prologue: float4 gate vectors (i,f,g,o per unit), Whh B-frags ----
    for (int i = tid; i < 104; i += THREADS) {
        float uu = 0.f, vv = 0.f;
        if (i < 100) {
            int u = i >> 2, gate = i & 3;
            int row = gate * HID + j0 + u;
            uu = g_u[dir][row];
            vv = g_v[dir][row];
        }
        su4f[i] = uu;
        sv4f[i] = vv;
    }
    // Bp[(kc*13+nsub)*32+lane]: b0 = fp16x2{W(n,k0),W(n,k0+1)}, b1 = {W(n,k0+8),W(n,k0+9)}
    // gate-interleaved packed n = nsub*8 + (lane>>2): u = n>>2, gate = n&3
    for (int i = tid; i < KC_N * NSUB * 32; i += THREADS) {
        int kc = i / (NSUB * 32);
        int r  = i % (NSUB * 32);
        int nsub = r >> 5;
        int lane = r & 31;
        int g = lane >> 2, tg = lane & 3;
        int n = nsub * 8 + g;
        int u = n >> 2, gate = n & 3;
        float w0 = 0.f, w1 = 0.f, w2 = 0.f, w3 = 0.f;
        if (u < UNITS_PER) {
            int row = gate * HID + j0 + u;
            int k0 = kc * 16 + 2 * tg;
            const float* wr = &Whh[row * HID];
            if (k0     < HID) w0 = wr[k0];
            if (k0 + 1 < HID) w1 = wr[k0 + 1];
            if (k0 + 8 < HID) w2 = wr[k0 + 8];
            if (k0 + 9 < HID) w3 = wr[k0 + 9];
        }
        Bp[i] = make_uint2(pack_h2(w0, w1), pack_h2(w2, w3));
    }
    __syncthreads();
    asm volatile("barrier.cluster.arrive.aligned;" ::: "memory");
    asm volatile("barrier.cluster.wait.aligned;" ::: "memory");

    const int warp = tid >> 5;
    const int lane = tid & 31;
    const int mt = warp & 3;   // m16 tile within 64 rows
    const int nh = warp >> 2;  // 0: subtiles 0-6, 1: subtiles 7-12
    const int qd = tid >> 6;   // Phase D: u ≡ qd (mod 4)  (warp-uniform)
    const int bd = tid & 63;   // Phase D: fixed batch row

    float creg[7];
    #pragma unroll
    for (int j = 0; j < 7; j++) creg[j] = 0.f;

    for (int s = 0; s < T_STEPS; s++) {
        const int p = s & 1;
        const int t = dir ? (T_STEPS - 1 - s) : s;
        const uint32_t* fin = &g_hfrag[p][dir][bt][0];
        unsigned short* fout = (unsigned short*)&g_hfrag[p ^ 1][dir][bt][0];

        // per-thread x scalar for Phase D (issued early, hides behind MMA)
        const float xi = __ldg(&x[t * BATCH + bt * BT_ROWS + bd]);

        // ---- Phase B+C: MMA into gate-interleaved Gbuf ----
        if (nh == 0) phaseBC<7>(fin, Bp, Gbuf, mt, 0, lane);
        else         phaseBC<6>(fin, Bp, Gbuf, mt, 7, lane);
        __syncthreads();

        // ---- Phase D: fixed (b, u-set) per thread; c and h in registers ----
        float hreg[7];
        {
            const float* grow = &Gbuf[bd * GSTRIDE];
            #pragma unroll
            for (int jj = 0; jj < 7; jj++) {
                int u = qd + jj * 4;
                if (u < UNITS_PER) {
                    float4 gq = *(const float4*)&grow[4 * u];
                    float4 a4 = su4[u];
                    float4 v4 = sv4[u];
                    float gi = gq.x + xi * a4.x + v4.x;
                    float gf = gq.y + xi * a4.y + v4.y;
                    float gg = gq.z + xi * a4.z + v4.z;
                    float go = gq.w + xi * a4.w + v4.w;
                    float cn = sigf(gf) * creg[jj] + sigf(gi) * tanha(gg);
                    creg[jj] = cn;
                    float h = sigf(go) * tanha(cn);
                    hreg[jj] = h;
                    // fp16 fragment half address for (bd, k=j0+u)
                    int k = j0 + u;
                    int mtt = bd >> 4, g2 = bd & 7, rb = (bd >> 3) & 1;
                    int kc = k >> 4, km = k & 15;
                    int tg = (km >> 1) & 3, kb = km >> 3, half = k & 1;
                    int ln = (g2 << 2) | tg;
                    int reg = (kb << 1) | rb;
                    int idx16 = ((((kc * 4 + mtt) << 5) | ln) * 4 + reg) * 2 + half;
                    __half hh = __float2half_rn(h);
                    fout[idx16] = *(unsigned short*)&hh;
                }
            }
        }

        // ---- arrive: per-thread release of this thread's h-frag stores.
        //      (No CTA sync needed: cluster wait below re-syncs the CTA.) ----
        asm volatile("barrier.cluster.arrive.aligned;" ::: "memory");

        // ---- Phase E: in-warp batch reduce + uncontended red.global.add ----
        #pragma unroll
        for (int jj = 0; jj < 7; jj++) {
            int u = qd + jj * 4;                 // warp-uniform
            if (u < UNITS_PER) {
                float v = hreg[jj];
                v += __shfl_down_sync(0xffffffffu, v, 16);
                v += __shfl_down_sync(0xffffffffu, v, 8);
                v += __shfl_down_sync(0xffffffffu, v, 4);
                v += __shfl_down_sync(0xffffffffu, v, 2);
                v += __shfl_down_sync(0xffffffffu, v, 1);
                if (lane == 0)
                    asm volatile("red.global.add.f32 [%0], %1;"
                                 :: "l"(&g_hpart[dir][bt][t][j0 + u]), "f"(v)
                                 : "memory");
            }
        }

        // ---- wait: all 8 CTAs (all threads) arrived -> h exchange complete ----
        asm volatile("barrier.cluster.wait.aligned;" ::: "memory");
    }
}

// ---------------- finalize: reduce partials over bt, apply linear head ----------------
__global__ void finalize_kernel(const float* __restrict__ W_fc,
                                const float* __restrict__ b_fc,
                                float* __restrict__ out) {
    __shared__ float hb[2 * HID];
    int t = blockIdx.x;
    int tid = threadIdx.x;
    for (int j = tid; j < 2 * HID; j += blockDim.x) {
        int dir = j / HID, jj = j - dir * HID;
        float sum = 0.f;
        #pragma unroll
        for (int b = 0; b < 8; b++) sum += g_hpart[dir][b][t][jj];
        hb[j] = sum;
    }
    __syncthreads();
    if (tid < 10) {
        const float* wf = &W_fc[tid * (2 * HID)];
        float acc = 0.f;
        for (int j = 0; j < 2 * HID; j++) acc += wf[j] * hb[j];
        out[t * 10 + tid] = b_fc[tid] + acc * (1.f / 512.f);
    }
}

extern "C" void kernel_launch(void* const* d_in, const int* in_sizes, int n_in,
                              void* d_out, int out_size) {
    const float* x     = (const float*)d_in[0];
    const float* W_in  = (const float*)d_in[1];
    const float* b_in  = (const float*)d_in[2];
    const float* Wih_f = (const float*)d_in[3];
    const float* Whh_f = (const float*)d_in[4];
    const float* b_f   = (const float*)d_in[5];
    const float* Wih_b = (const float*)d_in[6];
    const float* Whh_b = (const float*)d_in[7];
    const float* b_b   = (const float*)d_in[8];
    const float* W_fc  = (const float*)d_in[9];
    const float* b_fc  = (const float*)d_in[10];
    float* out = (float*)d_out;

    cudaFuncSetAttribute(lstm_kernel,
                         cudaFuncAttributeMaxDynamicSharedMemorySize, SMEM_BYTES);

    precompute_kernel<<<32, 256>>>(W_in, b_in, Wih_f, b_f, Wih_b, b_b);
    lstm_kernel<<<NCTA, THREADS, SMEM_BYTES>>>(x, Whh_f, Whh_b);
    finalize_kernel<<<T_STEPS, 256>>>(W_fc, b_fc, out);
}

// round 17
// speedup vs baseline: 1.4782x; 1.0698x over previous
#include <cuda_runtime.h>
#include <cuda_fp16.h>
#include <cstdint>

#define T_STEPS 784
#define BATCH   512
#define HID     200
#define G4      800
#define NCTA    128
#define THREADS 256
#define UNITS_PER 25
#define BT_ROWS 64
#define KC_N    13              // ceil(200/16) k-chunks of 16
#define NSUB    13              // gate-interleaved packed N = 104 (100 real)
#define FRAG_U32 (KC_N*4*32*4)  // 6656 uint32 words per (parity,dir,bt) block

// ---------------- device global scratch (static, no allocation) ----------------
__device__ float g_u[2][G4];
__device__ float g_v[2][G4];
__device__ uint32_t g_hfrag[2][2][8][FRAG_U32];   // fp16x2 A-fragment words
__device__ float g_hpart[2][8][T_STEPS][HID];     // per-(dir,bt) batch partial sums

// ---------------- smem layout (bytes) ----------------
#define GSTRIDE 108       // floats per Gbuf row (104 used, 16B-unit stride 27 = conflict-free)
#define BP_OFF 0          // uint2 [13][13][32]    43264
#define GB_OFF 43264      // float [64][108]       27648
#define HS_OFF 70912      // float [64][26]         6656
#define SU_OFF 77568      // float4 [26]             416
#define SV_OFF 77984      // float4 [26]             416
#define PS_OFF 78400      // float [200]             800
#define SMEM_BYTES 79200

__device__ __forceinline__ float tanha(float x) {
    float r;
    asm("tanh.approx.f32 %0, %1;" : "=f"(r) : "f"(x));
    return r;
}
__device__ __forceinline__ float sigf(float x) {
    return fmaf(0.5f, tanha(0.5f * x), 0.5f);
}
__device__ __forceinline__ uint32_t pack_h2(float lo, float hi) {
    __half2 h = __floats2half2_rn(lo, hi);
    return *(uint32_t*)&h;
}
__device__ __forceinline__ uint4 ldg_cg_v4(const uint32_t* p) {
    uint4 v;
    asm volatile("ld.global.cg.v4.u32 {%0,%1,%2,%3}, [%4];"
                 : "=r"(v.x), "=r"(v.y), "=r"(v.z), "=r"(v.w) : "l"(p));
    return v;
}

// ---------------- Phase B+C: m16 x n(8*JCNT), B LDS pipelined 1 kc ahead ----------------
template<int JCNT>
__device__ __forceinline__ void phaseBC(const uint32_t* __restrict__ fin,
                                        const uint2* __restrict__ Bp,
                                        float* __restrict__ Gbuf,
                                        int mt, int jbase, int lane) {
    const int ab = ((mt << 5) | lane) * 4;
    uint4 areg[KC_N];
    #pragma unroll
    for (int kc = 0; kc < KC_N; kc++)
        areg[kc] = ldg_cg_v4(fin + ab + kc * 512);

    float acc[JCNT][4];
    #pragma unroll
    for (int j = 0; j < JCNT; j++)
        acc[j][0] = acc[j][1] = acc[j][2] = acc[j][3] = 0.f;

    uint2 bb[JCNT];
    #pragma unroll
    for (int j = 0; j < JCNT; j++)
        bb[j] = Bp[(jbase + j) * 32 + lane];

    #pragma unroll
    for (int kc = 0; kc < KC_N; kc++) {
        uint2 bn[JCNT];
        if (kc + 1 < KC_N) {
            #pragma unroll
            for (int j = 0; j < JCNT; j++)
                bn[j] = Bp[((kc + 1) * NSUB + jbase + j) * 32 + lane];
        }
        #pragma unroll
        for (int j = 0; j < JCNT; j++) {
            asm volatile(
                "mma.sync.aligned.m16n8k16.row.col.f32.f16.f16.f32 "
                "{%0,%1,%2,%3}, {%4,%5,%6,%7}, {%8,%9}, {%0,%1,%2,%3};\n"
                : "+f"(acc[j][0]), "+f"(acc[j][1]), "+f"(acc[j][2]), "+f"(acc[j][3])
                : "r"(areg[kc].x), "r"(areg[kc].y), "r"(areg[kc].z), "r"(areg[kc].w),
                  "r"(bb[j].x), "r"(bb[j].y));
        }
        if (kc + 1 < KC_N) {
            #pragma unroll
            for (int j = 0; j < JCNT; j++) bb[j] = bn[j];
        }
    }
    int g = lane >> 2, tg = lane & 3;
    int row0 = mt * 16 + g;
    #pragma unroll
    for (int j = 0; j < JCNT; j++) {
        int col = (jbase + j) * 8 + tg * 2;
        *(float2*)&Gbuf[row0 * GSTRIDE + col]       = make_float2(acc[j][0], acc[j][1]);
        *(float2*)&Gbuf[(row0 + 8) * GSTRIDE + col] = make_float2(acc[j][2], acc[j][3]);
    }
}

// ---------------- precompute: rank-1 input-gate vectors + zeroing ----------------
__global__ void precompute_kernel(const float* __restrict__ W_in,
                                  const float* __restrict__ b_in,
                                  const float* __restrict__ Wih_f,
                                  const float* __restrict__ b_f,
                                  const float* __restrict__ Wih_b,
                                  const float* __restrict__ b_b) {
    int idx = blockIdx.x * blockDim.x + threadIdx.x;
    int nth = gridDim.x * blockDim.x;
    for (int i = idx; i < 2 * G4; i += nth) {
        int dir = i / G4, row = i % G4;
        const float* Wih = dir ? Wih_b : Wih_f;
        const float* bb  = dir ? b_b   : b_f;
        float su = 0.f, sv = 0.f;
        for (int k = 0; k < HID; k++) {
            float w = Wih[row * HID + k];
            su += w * W_in[k];
            sv += w * b_in[k];
        }
        g_u[dir][row] = su;
        g_v[dir][row] = sv + bb[row];
    }
    uint32_t* hf = &g_hfrag[0][0][0][0];
    for (int i = idx; i < 2 * 2 * 8 * FRAG_U32; i += nth) hf[i] = 0u;
}

// ---------------- persistent recurrence kernel: 16 clusters of 8 CTAs ----------------
__global__ void __launch_bounds__(THREADS, 1) __cluster_dims__(8, 1, 1)
lstm_kernel(const float* __restrict__ x,
            const float* __restrict__ Whh_f,
            const float* __restrict__ Whh_b) {
    extern __shared__ unsigned char smem_raw[];
    uint2*  Bp   = (uint2*) (smem_raw + BP_OFF);
    float*  Gbuf = (float*) (smem_raw + GB_OFF);
    float*  hsb  = (float*) (smem_raw + HS_OFF);
    float4* su4  = (float4*)(smem_raw + SU_OFF);
    float4* sv4  = (float4*)(smem_raw + SV_OFF);
    float*  psum = (float*) (smem_raw + PS_OFF);
    float*  su4f = (float*)su4;
    float*  sv4f = (float*)sv4;

    const int tid = threadIdx.x;
    const int cta = blockIdx.x;
    const int dir = cta >> 6;
    const int bt  = (cta >> 3) & 7;
    const int ut  = cta & 7;
    const int j0  = ut * UNITS_PER;
    const float* Whh = dir ? Whh_b : Whh_f;

    // ---- prologue: float4 gate vectors (i,f,g,o per unit), Whh B-frags ----
    for (int i = tid; i < 104; i += THREADS) {
        float uu = 0.f, vv = 0.f;
        if (i < 100) {
            int u = i >> 2, gate = i & 3;
            int row = gate * HID + j0 + u;
            uu = g_u[dir][row];
            vv = g_v[dir][row];
        }
        su4f[i] = uu;
        sv4f[i] = vv;
    }
    // Bp[(kc*13+nsub)*32+lane]: b0 = fp16x2{W(n,k0),W(n,k0+1)}, b1 = {W(n,k0+8),W(n,k0+9)}
    // gate-interleaved packed n = nsub*8 + (lane>>2): u = n>>2, gate = n&3
    for (int i = tid; i < KC_N * NSUB * 32; i += THREADS) {
        int kc = i / (NSUB * 32);
        int r  = i % (NSUB * 32);
        int nsub = r >> 5;
        int lane = r & 31;
        int g = lane >> 2, tg = lane & 3;
        int n = nsub * 8 + g;
        int u = n >> 2, gate = n & 3;
        float w0 = 0.f, w1 = 0.f, w2 = 0.f, w3 = 0.f;
        if (u < UNITS_PER) {
            int row = gate * HID + j0 + u;
            int k0 = kc * 16 + 2 * tg;
            const float* wr = &Whh[row * HID];
            if (k0     < HID) w0 = wr[k0];
            if (k0 + 1 < HID) w1 = wr[k0 + 1];
            if (k0 + 8 < HID) w2 = wr[k0 + 8];
            if (k0 + 9 < HID) w3 = wr[k0 + 9];
        }
        Bp[i] = make_uint2(pack_h2(w0, w1), pack_h2(w2, w3));
    }
    __syncthreads();
    asm volatile("barrier.cluster.arrive.aligned;" ::: "memory");
    asm volatile("barrier.cluster.wait.aligned;" ::: "memory");

    const int warp = tid >> 5;
    const int lane = tid & 31;
    const int mt = warp & 3;   // m16 tile within 64 rows
    const int nh = warp >> 2;  // 0: subtiles 0-6, 1: subtiles 7-12
    const int qd = tid >> 6;   // Phase D: u ≡ qd (mod 4)
    const int bd = tid & 63;   // Phase D: fixed batch row

    float creg[7];
    #pragma unroll
    for (int j = 0; j < 7; j++) creg[j] = 0.f;

    for (int s = 0; s < T_STEPS; s++) {
        const int p = s & 1;
        const int t = dir ? (T_STEPS - 1 - s) : s;
        const uint32_t* fin = &g_hfrag[p][dir][bt][0];
        unsigned short* fout = (unsigned short*)&g_hfrag[p ^ 1][dir][bt][0];

        // per-thread x scalar for Phase D (issued early, hides behind MMA)
        const float xi = __ldg(&x[t * BATCH + bt * BT_ROWS + bd]);

        // ---- Phase B+C: MMA into gate-interleaved Gbuf ----
        if (nh == 0) phaseBC<7>(fin, Bp, Gbuf, mt, 0, lane);
        else         phaseBC<6>(fin, Bp, Gbuf, mt, 7, lane);
        __syncthreads();

        // ---- Phase D: fixed (b, u-set) per thread; c in registers ----
        {
            const float* grow = &Gbuf[bd * GSTRIDE];
            #pragma unroll
            for (int jj = 0; jj < 7; jj++) {
                int u = qd + jj * 4;
                if (u < UNITS_PER) {
                    float4 gq = *(const float4*)&grow[4 * u];
                    float4 a4 = su4[u];
                    float4 v4 = sv4[u];
                    float gi = gq.x + xi * a4.x + v4.x;
                    float gf = gq.y + xi * a4.y + v4.y;
                    float gg = gq.z + xi * a4.z + v4.z;
                    float go = gq.w + xi * a4.w + v4.w;
                    float cn = sigf(gf) * creg[jj] + sigf(gi) * tanha(gg);
                    creg[jj] = cn;
                    float h = sigf(go) * tanha(cn);
                    hsb[bd * 26 + u] = h;
                    // fp16 fragment half address for (bd, k=j0+u)
                    int k = j0 + u;
                    int mtt = bd >> 4, g2 = bd & 7, rb = (bd >> 3) & 1;
                    int kc = k >> 4, km = k & 15;
                    int tg = (km >> 1) & 3, kb = km >> 3, half = k & 1;
                    int ln = (g2 << 2) | tg;
                    int reg = (kb << 1) | rb;
                    int idx16 = ((((kc * 4 + mtt) << 5) | ln) * 4 + reg) * 2 + half;
                    __half hh = __float2half_rn(h);
                    fout[idx16] = *(unsigned short*)&hh;
                }
            }
        }
        __syncthreads();

        // ---- arrive (release h-frag stores), overlap Phase E with peer skew ----
        asm volatile("barrier.cluster.arrive.aligned;" ::: "memory");

        // ---- Phase E: batch partial sums -> uncontended global partials ----
        if (tid < 200) {
            int u = tid >> 3;
            int seg = tid & 7;
            float sum = 0.f;
            #pragma unroll
            for (int b = 0; b < 8; b++) sum += hsb[(seg * 8 + b) * 26 + u];
            psum[tid] = sum;
        }
        __syncthreads();
        if (tid < UNITS_PER) {
            float sum = 0.f;
            #pragma unroll
            for (int k = 0; k < 8; k++) sum += psum[tid * 8 + k];
            g_hpart[dir][bt][t][j0 + tid] = sum;
        }

        // ---- wait: acquire all 8 CTAs' h writes ----
        asm volatile("barrier.cluster.wait.aligned;" ::: "memory");
    }
}

// ---------------- finalize: reduce partials over bt, apply linear head ----------------
__global__ void finalize_kernel(const float* __restrict__ W_fc,
                                const float* __restrict__ b_fc,
                                float* __restrict__ out) {
    __shared__ float hb[2 * HID];
    int t = blockIdx.x;
    int tid = threadIdx.x;
    for (int j = tid; j < 2 * HID; j += blockDim.x) {
        int dir = j / HID, jj = j - dir * HID;
        float sum = 0.f;
        #pragma unroll
        for (int b = 0; b < 8; b++) sum += g_hpart[dir][b][t][jj];
        hb[j] = sum;
    }
    __syncthreads();
    if (tid < 10) {
        const float* wf = &W_fc[tid * (2 * HID)];
        float acc = 0.f;
        for (int j = 0; j < 2 * HID; j++) acc += wf[j] * hb[j];
        out[t * 10 + tid] = b_fc[tid] + acc * (1.f / 512.f);
    }
}

extern "C" void kernel_launch(void* const* d_in, const int* in_sizes, int n_in,
                              void* d_out, int out_size) {
    const float* x     = (const float*)d_in[0];
    const float* W_in  = (const float*)d_in[1];
    const float* b_in  = (const float*)d_in[2];
    const float* Wih_f = (const float*)d_in[3];
    const float* Whh_f = (const float*)d_in[4];
    const float* b_f   = (const float*)d_in[5];
    const float* Wih_b = (const float*)d_in[6];
    const float* Whh_b = (const float*)d_in[7];
    const float* b_b   = (const float*)d_in[8];
    const float* W_fc  = (const float*)d_in[9];
    const float* b_fc  = (const float*)d_in[10];
    float* out = (float*)d_out;

    cudaFuncSetAttribute(lstm_kernel,
                         cudaFuncAttributeMaxDynamicSharedMemorySize, SMEM_BYTES);

    precompute_kernel<<<32, 256>>>(W_in, b_in, Wih_f, b_f, Wih_b, b_b);
    lstm_kernel<<<NCTA, THREADS, SMEM_BYTES>>>(x, Whh_f, Whh_b);
    finalize_kernel<<<T_STEPS, 256>>>(W_fc, b_fc, out);
}